// round 4
// baseline (speedup 1.0000x reference)
#include <cuda_runtime.h>

#define NB   32
#define NF   500
#define NS   80000      // NF * 160
#define NROWS 16000     // NB * NF

// scratch (no allocation allowed -> __device__ global)
__device__ float g_w[NROWS * 64];     // final filters w[b,f][o*32 + i*16 + k]

#define FFMA2(acc, a, b) \
    asm("fma.rn.f32x2 %0, %1, %2, %0;" : "+l"(acc) : "l"(a), "l"(b))
#define PACK2(dst, lo, hi) \
    asm("mov.b64 %0, {%1, %2};" : "=l"(dst) : "f"(lo), "f"(hi))
#define DUP2(dst, v) \
    asm("mov.b64 %0, {%1, %1};" : "=l"(dst) : "f"(v))
#define UNPACK2(lo, hi, src) \
    asm("mov.b64 {%0, %1}, %2;" : "=f"(lo), "=f"(hi) : "l"(src))

// ---------------------------------------------------------------------------
// Kernel 1: fused GEMM + filter post-processing.
//   C[16000 x 72] = features[16000 x 256] @ W^T
//   W rows 0..63 = conv_kernel_w, 64..65 = filter_gain_w, 66..71 = zero pad.
// Block: 64 rows x 72 cols, 128 threads. Thread tile: 2 rows x 18 cols,
// accumulated as 2 x 9 packed f32x2 pairs via fma.rn.f32x2 (FFMA2).
// Epilogue (in-block): +bias, per-(row,o) L2 norm over 32 taps,
//   gain = exp(GA*tanh(z)), w = v*(SG*gain/(1e-6+norm)) + (1-SG)*gain*[k==7].
// ---------------------------------------------------------------------------
__global__ __launch_bounds__(128) void gemm_kernel(const float* __restrict__ feat,
                                                   const float* __restrict__ ckw,
                                                   const float* __restrict__ fgw,
                                                   const float* __restrict__ ckb,
                                                   const float* __restrict__ fgb)
{
    // mainloop view:  sfeat[32*66] | sw[32*72]   (4416 floats)
    // epilogue view:  sC[64*73]                  (4672 floats)
    __shared__ float smem[4672];
    __shared__ float sScale[64][2];   // per (row_local, o): multiplicative scale
    __shared__ float sAddG[64][2];    // per (row_local, o): (1-SG)*gain (id-tap add)
    float* sfeat = smem;              // [c_local][row], pitch 66
    float* sw    = smem + 32 * 66;    // [c_local][j],  pitch 72

    const int t = threadIdx.x;
    const int lane = t & 31;          // owns rows 2*lane, 2*lane+1
    const int ct = t >> 5;            // warp owns cols ct*18 .. ct*18+17
    const int r0 = blockIdx.x * 64;

    unsigned long long acc2[2][9];    // packed (col 2m, col 2m+1) accumulators
#pragma unroll
    for (int a = 0; a < 2; a++)
#pragma unroll
        for (int m = 0; m < 9; m++) acc2[a][m] = 0ull;

    for (int cc = 0; cc < 8; cc++) {
        const int c0 = cc * 32;
        __syncthreads();
        // features chunk, transposed into shared (coalesced global reads)
        for (int idx = t; idx < 2048; idx += 128) {
            int row = idx >> 5, cl = idx & 31;
            sfeat[cl * 66 + row] = feat[(r0 + row) * 256 + c0 + cl];
        }
        // weights chunk, transposed (coalesced along c)
        for (int idx = t; idx < 2304; idx += 128) {
            int cl = idx & 31, jj = idx >> 5;
            float v = 0.f;
            if (jj < 64)      v = ckw[jj * 256 + c0 + cl];
            else if (jj < 66) v = fgw[(jj - 64) * 256 + c0 + cl];
            sw[cl * 72 + jj] = v;
        }
        __syncthreads();
#pragma unroll
        for (int cp = 0; cp < 32; cp++) {
            float2 fv = *(const float2*)&sfeat[cp * 66 + 2 * lane];
            unsigned long long dx, dy;
            DUP2(dx, fv.x);
            DUP2(dy, fv.y);
            const unsigned long long* wrow =
                (const unsigned long long*)&sw[cp * 72 + ct * 18];
#pragma unroll
            for (int m = 0; m < 9; m++) {
                unsigned long long w2 = wrow[m];
                FFMA2(acc2[0][m], w2, dx);
                FFMA2(acc2[1][m], w2, dy);
            }
        }
    }

    // ---- epilogue: spill acc to shared C tile [64][73] -------------------
    __syncthreads();                  // mainloop smem reads done
    float* sC = smem;                 // pitch 73 (odd -> conflict-friendly)
#pragma unroll
    for (int rr = 0; rr < 2; rr++) {
        float* dst = &sC[(2 * lane + rr) * 73 + ct * 18];
#pragma unroll
        for (int m = 0; m < 9; m++) {
            float lo, hi;
            UNPACK2(lo, hi, acc2[rr][m]);
            dst[2 * m]     = lo;
            dst[2 * m + 1] = hi;
        }
    }
    __syncthreads();

    // ---- per-(row,o) scales: 128 threads = 64 rows x 2 channels ----------
    {
        const int row = t >> 1, o = t & 1;
        const float* Crow = &sC[row * 73 + o * 32];
        float ss = 0.f;
#pragma unroll
        for (int j = 0; j < 32; j++) {
            float v = Crow[j] + ckb[o * 32 + j];
            ss += v * v;
        }
        float z = sC[row * 73 + 64 + o] + fgb[o];
        const float GA = 0.6907755278982137f;   // (log_max-log_min)/2 ; gain_b = 0
        const float SG = 0.5011872336272722f;   // 10^(-6/20)
        float g  = expf(GA * tanhf(z));
        sScale[row][o] = SG * g / (1e-6f + sqrtf(ss));
        sAddG[row][o]  = (1.0f - SG) * g;
    }
    __syncthreads();

    // ---- coalesced scaled write of g_w -----------------------------------
    for (int idx = t; idx < 64 * 64; idx += 128) {
        int row = idx >> 6, col = idx & 63;
        int o = col >> 5;
        float v = sC[row * 73 + col] + ckb[col];
        float w = v * sScale[row][o];
        if ((col & 15) == 7) w += sAddG[row][o];    // id_tap = 7
        g_w[(r0 + row) * 64 + col] = w;
    }
}

// ---------------------------------------------------------------------------
// Kernel 2: time-domain conv + windowed overlap-add, fully fused.
// Block = (b, group of 4 frames). 160 threads = 40 quads/frame.
// Thread remap packs all overlap quads (s0 < 40, which also need the
// previous frame's tail conv) into t in [0,40) so only warps 0-1 pay the
// second conv pass (7 conv-pass-units/block instead of 10).
// Inner conv uses packed fma.rn.f32x2: ds accumulated as 2 f32x2 pairs.
// ---------------------------------------------------------------------------
__global__ __launch_bounds__(160) void conv_kernel(const float* __restrict__ x,
                                                   const float* __restrict__ owin,
                                                   float* __restrict__ out)
{
    __shared__ float xs[2 * 656];   // x[b,i, fbase*160-15 .. +640]  (656 entries)
    __shared__ float ws5[320];      // filters for frames fbase-1 .. fbase+3
    __shared__ float ow[40];
    const int t = threadIdx.x;
    const int b = blockIdx.y;
    const int fbase = blockIdx.x * 4;
    const int g0 = fbase * 160 - 15;

    for (int i = 0; i < 2; i++)
        for (int idx = t; idx < 656; idx += 160) {
            int g = g0 + idx;
            xs[i * 656 + idx] = (g >= 0 && g < NS) ? x[(b * 2 + i) * NS + g] : 0.f;
        }
    {
        int base = (b * NF + fbase - 1) * 64;
        for (int idx = t; idx < 320; idx += 160) {
            int src = base + idx;
            ws5[idx] = (src >= 0) ? g_w[src] : 0.f;
        }
    }
    if (t < 40) ow[t] = owin[t];
    __syncthreads();

    // ---- thread remap: overlap quads first --------------------------------
    int fl, s0;
    bool ov;
    if (t < 40) {                    // overlap region: 4 frames x 10 quads
        ov = true;
        fl = t / 10;
        s0 = (t - fl * 10) * 4;      // 0..36
    } else {                         // non-overlap: 4 frames x 30 quads
        ov = false;
        int u = t - 40;
        fl = u / 30;
        s0 = 40 + (u - fl * 30) * 4; // 40..156
    }
    const int base = fl * 160 + s0;  // xs index of x[.., f*160 + s0 - 15]

    float xr[2][20];                 // xr[i][0..18] used; [19] is slack
#pragma unroll
    for (int i = 0; i < 2; i++) {
        const float4* xp = (const float4*)&xs[i * 656 + base];
#pragma unroll
        for (int q = 0; q < 5; q++) {
            float4 v = xp[q];
            xr[i][4 * q]     = v.x;
            xr[i][4 * q + 1] = v.y;
            xr[i][4 * q + 2] = v.z;
            xr[i][4 * q + 3] = v.w;
        }
    }

    // ---- current-frame conv, packed f32x2 ---------------------------------
    const float* wc = &ws5[(1 + fl) * 64];
    unsigned long long a0[2] = {0ull, 0ull};   // o=0: (ds0,ds1),(ds2,ds3)
    unsigned long long a1[2] = {0ull, 0ull};   // o=1
#pragma unroll
    for (int i = 0; i < 2; i++)
#pragma unroll
        for (int k = 0; k < 16; k++) {
            const int m = 15 - k;
            unsigned long long pxa, pxb, wd0, wd1;
            PACK2(pxa, xr[i][m],     xr[i][m + 1]);
            PACK2(pxb, xr[i][m + 2], xr[i][m + 3]);
            DUP2(wd0, wc[i * 16 + k]);
            DUP2(wd1, wc[32 + i * 16 + k]);
            FFMA2(a0[0], wd0, pxa);
            FFMA2(a0[1], wd0, pxb);
            FFMA2(a1[0], wd1, pxa);
            FFMA2(a1[1], wd1, pxb);
        }

    // ---- previous-frame tail conv (overlap threads only) ------------------
    unsigned long long p0[2] = {0ull, 0ull};
    unsigned long long p1[2] = {0ull, 0ull};
    if (ov && (fbase + fl > 0)) {
        const float* wp = &ws5[fl * 64];
#pragma unroll
        for (int i = 0; i < 2; i++)
#pragma unroll
            for (int k = 0; k < 16; k++) {
                const int m = 15 - k;
                unsigned long long pxa, pxb, wd0, wd1;
                PACK2(pxa, xr[i][m],     xr[i][m + 1]);
                PACK2(pxb, xr[i][m + 2], xr[i][m + 3]);
                DUP2(wd0, wp[i * 16 + k]);
                DUP2(wd1, wp[32 + i * 16 + k]);
                FFMA2(p0[0], wd0, pxa);
                FFMA2(p0[1], wd0, pxb);
                FFMA2(p1[0], wd1, pxa);
                FFMA2(p1[1], wd1, pxb);
            }
    }

    // ---- unpack, window, write -------------------------------------------
    float av0[4], av1[4], pv0[4], pv1[4];
    UNPACK2(av0[0], av0[1], a0[0]); UNPACK2(av0[2], av0[3], a0[1]);
    UNPACK2(av1[0], av1[1], a1[0]); UNPACK2(av1[2], av1[3], a1[1]);
    UNPACK2(pv0[0], pv0[1], p0[0]); UNPACK2(pv0[2], pv0[3], p0[1]);
    UNPACK2(pv1[0], pv1[1], p1[0]); UNPACK2(pv1[2], pv1[3], p1[1]);

    float r0[4], r1[4];
#pragma unroll
    for (int ds = 0; ds < 4; ds++) {
        if (ov) {
            int s = s0 + ds;
            float hw = ow[39 - s];               // win1 = flip(overlap_win)
            float tw = ow[s];                    // win2 = overlap_win
            r0[ds] = av0[ds] * hw + pv0[ds] * tw;
            r1[ds] = av1[ds] * hw + pv1[ds] * tw;
        } else {
            r0[ds] = av0[ds];
            r1[ds] = av1[ds];
        }
    }
    const int off = (fbase + fl) * 160 + s0;
    *(float4*)&out[(b * 2 + 0) * NS + off] = make_float4(r0[0], r0[1], r0[2], r0[3]);
    *(float4*)&out[(b * 2 + 1) * NS + off] = make_float4(r1[0], r1[1], r1[2], r1[3]);
}

extern "C" void kernel_launch(void* const* d_in, const int* in_sizes, int n_in,
                              void* d_out, int out_size)
{
    const float* x    = (const float*)d_in[0];
    const float* feat = (const float*)d_in[1];
    const float* ckw  = (const float*)d_in[2];
    const float* ckb  = (const float*)d_in[3];
    const float* fgw  = (const float*)d_in[4];
    const float* fgb  = (const float*)d_in[5];
    const float* owin = (const float*)d_in[6];
    float* out = (float*)d_out;

    gemm_kernel<<<250, 128>>>(feat, ckw, fgw, ckb, fgb);
    conv_kernel<<<dim3(125, 32), 160>>>(x, owin, out);
}

// round 7
// speedup vs baseline: 1.1939x; 1.1939x over previous
#include <cuda_runtime.h>

#define NB   32
#define NF   500
#define NS   80000      // NF * 160
#define NROWS 16000     // NB * NF

typedef unsigned long long ull;

// scratch (no allocation allowed -> __device__ global)
__device__ float g_w[NROWS * 64];     // final filters w[b,f][o*32 + i*16 + k]

#define FFMA2(acc, a, b) \
    asm("fma.rn.f32x2 %0, %1, %2, %0;" : "+l"(acc) : "l"(a), "l"(b))
#define DUP2(dst, v) \
    asm("mov.b64 %0, {%1, %1};" : "=l"(dst) : "f"(v))
#define UNPACK2(lo, hi, src) \
    asm("mov.b64 {%0, %1}, %2;" : "=f"(lo), "=f"(hi) : "l"(src))

// ---------------------------------------------------------------------------
// Kernel 1: fused GEMM + filter post-processing (double-buffered).
//   C[16000 x 80pad] = features[16000 x 256] @ W^T   (cols 66..79 zero-pad)
//   W rows 0..63 = conv_kernel_w, 64..65 = filter_gain_w.
// Block: 64 rows x 80 cols, 256 threads (8 warps). Thread: 2 rows x 10 cols.
// Double buffer: prefetch chunk cc+1 into registers during compute of cc.
// Epilogue (in-block): +bias, per-(row,o) L2 norm over 32 taps,
//   gain = exp(GA*tanh(z)), w = v*(SG*gain/(1e-6+norm)) + (1-SG)*gain*[k==7].
// ---------------------------------------------------------------------------
#define GDB 4672   // per-buffer floats: 32*66 (sfeat) + 32*80 (sw)
__global__ __launch_bounds__(256) void gemm_kernel(const float* __restrict__ feat,
                                                   const float* __restrict__ ckw,
                                                   const float* __restrict__ fgw,
                                                   const float* __restrict__ ckb,
                                                   const float* __restrict__ fgb)
{
    __shared__ __align__(16) float smem[2 * GDB];   // 37.4 KB; epilogue reuses [0..5183]
    __shared__ float sScale[64][2];
    __shared__ float sAddG[64][2];

    const int t = threadIdx.x;
    const int lane = t & 31;          // owns rows 2*lane, 2*lane+1
    const int wid = t >> 5;           // warp owns cols wid*10 .. wid*10+9
    const int r0 = blockIdx.x * 64;

    ull acc2[2][5];
#pragma unroll
    for (int a = 0; a < 2; a++)
#pragma unroll
        for (int m = 0; m < 5; m++) acc2[a][m] = 0ull;

    // fill chunk 0 into buffer 0
    for (int idx = t; idx < 2048; idx += 256) {
        int row = idx >> 5, cl = idx & 31;
        smem[cl * 66 + row] = feat[(r0 + row) * 256 + cl];
    }
    for (int idx = t; idx < 2560; idx += 256) {
        int cl = idx & 31, jj = idx >> 5;
        float v = 0.f;
        if (jj < 64)      v = ckw[jj * 256 + cl];
        else if (jj < 66) v = fgw[(jj - 64) * 256 + cl];
        smem[2112 + cl * 80 + jj] = v;
    }
    __syncthreads();

    for (int cc = 0; cc < 8; cc++) {
        float rf[8], rw[10];
        if (cc < 7) {                         // prefetch chunk cc+1 to regs
            const int c0 = (cc + 1) * 32;
#pragma unroll
            for (int q = 0; q < 8; q++) {
                int idx = t + q * 256;
                rf[q] = feat[(r0 + (idx >> 5)) * 256 + c0 + (idx & 31)];
            }
#pragma unroll
            for (int q = 0; q < 10; q++) {
                int idx = t + q * 256;
                int cl = idx & 31, jj = idx >> 5;
                float v = 0.f;
                if (jj < 64)      v = ckw[jj * 256 + c0 + cl];
                else if (jj < 66) v = fgw[(jj - 64) * 256 + c0 + cl];
                rw[q] = v;
            }
        }
        const float* buf   = smem + (cc & 1) * GDB;
        const float* sfeat = buf;
        const float* sw    = buf + 2112;
#pragma unroll
        for (int cp = 0; cp < 32; cp++) {
            float2 fv = *(const float2*)&sfeat[cp * 66 + 2 * lane];
            ull dx, dy;
            DUP2(dx, fv.x);
            DUP2(dy, fv.y);
            const ull* wrow = (const ull*)&sw[cp * 80 + wid * 10];
#pragma unroll
            for (int m = 0; m < 5; m++) {
                ull w2 = wrow[m];
                FFMA2(acc2[0][m], w2, dx);
                FFMA2(acc2[1][m], w2, dy);
            }
        }
        if (cc < 7) {                         // store prefetched regs to other buffer
            float* nbuf = smem + ((cc + 1) & 1) * GDB;
#pragma unroll
            for (int q = 0; q < 8; q++) {
                int idx = t + q * 256;
                nbuf[(idx & 31) * 66 + (idx >> 5)] = rf[q];
            }
#pragma unroll
            for (int q = 0; q < 10; q++) {
                int idx = t + q * 256;
                nbuf[2112 + (idx & 31) * 80 + (idx >> 5)] = rw[q];
            }
        }
        __syncthreads();
    }

    // ---- epilogue: spill acc to shared C tile [64][81] -------------------
    float* sC = smem;                 // pitch 81 (odd)
#pragma unroll
    for (int rr = 0; rr < 2; rr++) {
        float* dst = &sC[(2 * lane + rr) * 81 + wid * 10];
#pragma unroll
        for (int m = 0; m < 5; m++) {
            float lo, hi;
            UNPACK2(lo, hi, acc2[rr][m]);
            dst[2 * m]     = lo;
            dst[2 * m + 1] = hi;
        }
    }
    __syncthreads();

    if (t < 128) {
        const int row = t >> 1, o = t & 1;
        const float* Crow = &sC[row * 81 + o * 32];
        float ss = 0.f;
#pragma unroll
        for (int j = 0; j < 32; j++) {
            float v = Crow[j] + ckb[o * 32 + j];
            ss += v * v;
        }
        float z = sC[row * 81 + 64 + o] + fgb[o];
        const float GA = 0.6907755278982137f;   // (log_max-log_min)/2 ; gain_b = 0
        const float SG = 0.5011872336272722f;   // 10^(-6/20)
        float g  = expf(GA * tanhf(z));
        sScale[row][o] = SG * g / (1e-6f + sqrtf(ss));
        sAddG[row][o]  = (1.0f - SG) * g;
    }
    __syncthreads();

    for (int idx = t; idx < 64 * 64; idx += 256) {
        int row = idx >> 6, col = idx & 63;
        int o = col >> 5;
        float v = sC[row * 81 + col] + ckb[col];
        float w = v * sScale[row][o];
        if ((col & 15) == 7) w += sAddG[row][o];    // id_tap = 7
        g_w[(r0 + row) * 64 + col] = w;
    }
}

// ---------------------------------------------------------------------------
// Kernel 2: time-domain conv + windowed overlap-add.
// Block = (b, group of 8 frames), 160 threads, each computing 8 consecutive
// output samples for both output channels. Overlap threads (s0 < 40) are
// packed into t in [0,40) (warps 0-1 only) and also compute the previous
// frame's tail on the SAME x window.
// x window stored twice in smem (second copy shifted by 1 float) so both
// even-pair (A) and odd-pair (B) f32x2 operands load directly as
// ld.shared.v2.b64 -- no register packing movs at all.
// ---------------------------------------------------------------------------
__global__ __launch_bounds__(160) void conv_kernel(const float* __restrict__ x,
                                                   const float* __restrict__ owin,
                                                   float* __restrict__ out)
{
    __shared__ __align__(16) float xs [2][1300];  // xs [i][j] = x[b,i, g0+j],   j<1296
    __shared__ __align__(16) float xs2[2][1300];  // xs2[i][j] = x[b,i, g0+1+j], j<1296
    __shared__ __align__(16) float ws5[9 * 64];   // filters frames fbase-1 .. fbase+7
    __shared__ float ow[40];
    const int t = threadIdx.x;
    const int b = blockIdx.y;
    const int fbase = blockIdx.x * 8;
    const int g0 = fbase * 160 - 15;

    for (int i = 0; i < 2; i++)
        for (int idx = t; idx < 1297; idx += 160) {
            int g = g0 + idx;
            float v = (g >= 0 && g < NS) ? x[(b * 2 + i) * NS + g] : 0.f;
            if (idx < 1296) xs[i][idx] = v;
            if (idx >= 1)   xs2[i][idx - 1] = v;
        }
    {
        int basew = (b * NF + fbase - 1) * 64;
        for (int idx = t; idx < 576; idx += 160) {
            int src = basew + idx;
            ws5[idx] = (src >= 0 && src < NROWS * 64) ? g_w[src] : 0.f;
        }
    }
    if (t < 40) ow[t] = owin[t];
    __syncthreads();

    // thread remap: all overlap (s0<40) work in t<40 => warps 0-1 only
    int fl, s0;
    bool ov;
    if (t < 40) { ov = true;  fl = t / 5;  s0 = (t - fl * 5) * 8; }     // 0..32
    else { int u = t - 40; ov = false; fl = u / 15; s0 = 40 + (u - fl * 15) * 8; } // 40..152
    const int f = fbase + fl;
    const bool valid = f < NF;
    const int base = fl * 160 + s0;   // xs idx of x[.., f*160 + s0 - 15]

    ull a[2][4], pa[2][4];
#pragma unroll
    for (int o = 0; o < 2; o++)
#pragma unroll
        for (int q = 0; q < 4; q++) { a[o][q] = 0ull; pa[o][q] = 0ull; }

    const bool doprev = ov && valid && (f > 0);
    const float* wc = &ws5[(1 + fl) * 64];
    const float* wp = &ws5[fl * 64];

#pragma unroll
    for (int i = 0; i < 2; i++) {
        // A[p] = (x[s0-15+2p],   x[s0-15+2p+1])   p=0..11
        // B[p] = (x[s0-15+2p+1], x[s0-15+2p+2])   p=0..11
        ull A[12], Bp[12];
#pragma unroll
        for (int q = 0; q < 6; q++) {
            ulonglong2 va = *(const ulonglong2*)&xs [i][base + 4 * q];
            ulonglong2 vb = *(const ulonglong2*)&xs2[i][base + 4 * q];
            A [2 * q] = va.x;  A [2 * q + 1] = va.y;
            Bp[2 * q] = vb.x;  Bp[2 * q + 1] = vb.y;
        }
        // current-frame pass
#pragma unroll
        for (int k = 0; k < 16; k++) {
            ull w0d, w1d;
            DUP2(w0d, wc[i * 16 + k]);
            DUP2(w1d, wc[32 + i * 16 + k]);
#pragma unroll
            for (int q = 0; q < 4; q++) {
                const int j = 2 * q + 15 - k;          // pair (xr[j], xr[j+1])
                ull xv = (k & 1) ? A[j >> 1] : Bp[(j - 1) >> 1];
                FFMA2(a[0][q], w0d, xv);
                FFMA2(a[1][q], w1d, xv);
            }
        }
        // previous-frame tail pass (overlap threads only; same x packs)
        if (doprev) {
#pragma unroll
            for (int k = 0; k < 16; k++) {
                ull w0d, w1d;
                DUP2(w0d, wp[i * 16 + k]);
                DUP2(w1d, wp[32 + i * 16 + k]);
#pragma unroll
                for (int q = 0; q < 4; q++) {
                    const int j = 2 * q + 15 - k;
                    ull xv = (k & 1) ? A[j >> 1] : Bp[(j - 1) >> 1];
                    FFMA2(pa[0][q], w0d, xv);
                    FFMA2(pa[1][q], w1d, xv);
                }
            }
        }
    }

    if (valid) {
        float av[2][8], pv[2][8], r[2][8];
#pragma unroll
        for (int o = 0; o < 2; o++)
#pragma unroll
            for (int q = 0; q < 4; q++) {
                UNPACK2(av[o][2 * q], av[o][2 * q + 1], a[o][q]);
                UNPACK2(pv[o][2 * q], pv[o][2 * q + 1], pa[o][q]);
            }
        if (ov) {
#pragma unroll
            for (int d = 0; d < 8; d++) {
                int s = s0 + d;
                float hw = ow[39 - s];     // win1 = flip(overlap_win)
                float tw = ow[s];          // win2 = overlap_win
                r[0][d] = av[0][d] * hw + pv[0][d] * tw;
                r[1][d] = av[1][d] * hw + pv[1][d] * tw;
            }
        } else {
#pragma unroll
            for (int d = 0; d < 8; d++) { r[0][d] = av[0][d]; r[1][d] = av[1][d]; }
        }
        const int off = f * 160 + s0;
#pragma unroll
        for (int o = 0; o < 2; o++) {
            float* dst = &out[(b * 2 + o) * NS + off];
            *(float4*)&dst[0] = make_float4(r[o][0], r[o][1], r[o][2], r[o][3]);
            *(float4*)&dst[4] = make_float4(r[o][4], r[o][5], r[o][6], r[o][7]);
        }
    }
}

extern "C" void kernel_launch(void* const* d_in, const int* in_sizes, int n_in,
                              void* d_out, int out_size)
{
    const float* x    = (const float*)d_in[0];
    const float* feat = (const float*)d_in[1];
    const float* ckw  = (const float*)d_in[2];
    const float* ckb  = (const float*)d_in[3];
    const float* fgw  = (const float*)d_in[4];
    const float* fgb  = (const float*)d_in[5];
    const float* owin = (const float*)d_in[6];
    float* out = (float*)d_out;

    gemm_kernel<<<250, 256>>>(feat, ckw, fgw, ckb, fgb);
    conv_kernel<<<dim3(63, 32), 160>>>(x, owin, out);
}